// round 2
// baseline (speedup 1.0000x reference)
#include <cuda_runtime.h>
#include <math.h>
#include <stdint.h>

// ---------------------------------------------------------------------------
// Problem constants
// ---------------------------------------------------------------------------
#define NNODES 16384
#define KN     32
#define LDIM   128
#define PDIM   64
#define NKROWS (NNODES * KN)          // 524288 edge rows

// ---------------------------------------------------------------------------
// Scratch pool (static device memory; no allocations anywhere).
// Buffers aliased by liveness: total 375,390,208 floats (~1.50 GB),
// well below any 2^31 static-object boundary.
// ---------------------------------------------------------------------------
constexpr size_t F_ASELF = 0;                                   // [16384,512]
constexpr size_t F_ANB   = F_ASELF + 16384UL * 512;             // [16384,512]
constexpr size_t F_GPRE  = F_ANB   + 16384UL * 512;             // [16384,128]
constexpr size_t F_L1    = F_GPRE  + 16384UL * 128;             // [16384,128]
constexpr size_t F_U     = F_L1    + 16384UL * 128;             // [16384,512]
constexpr size_t F_V     = F_U     + 16384UL * 512;             // [16384,512]
constexpr size_t F_O     = F_V     + 16384UL * 512;             // [16384,128]
constexpr size_t F_MSG   = F_O     + 16384UL * 128;             // [524288,128]
constexpr size_t F_HG    = F_MSG   + 524288UL * 128;            // [524288,512]
constexpr size_t POOL_FLOATS = F_HG + 524288UL * 512;           // 375,390,208

// Phase-2 aliases (phase-1 buffers dead by then):
//   bself -> F_ASELF            (needs 16384*128, fits in aself's 8M)
//   bnb   -> F_ANB
//   hpg   -> F_HG + 0           (524288*128 = 64M floats)
//   hp2   -> F_HG + 67,108,864  (524288*64  = 32M floats)
//   gp    -> F_HG + 100,663,296 (524288*64  = 32M floats)   [hg holds 256M]
constexpr size_t F_BSELF = F_ASELF;
constexpr size_t F_BNB   = F_ANB;
constexpr size_t F_HPG   = F_HG;
constexpr size_t F_HP2   = F_HG + 524288UL * 128;
constexpr size_t F_GP    = F_HP2 + 524288UL * 64;

__device__ float g_pool[POOL_FLOATS];

// ---------------------------------------------------------------------------
// Math helpers (must match JAX: gelu approximate=True(tanh), silu, sigmoid)
// ---------------------------------------------------------------------------
__device__ __forceinline__ float gelu_tanh(float x) {
    const float c0 = 0.7978845608028654f;   // sqrt(2/pi)
    float x3 = x * x * x;
    return 0.5f * x * (1.0f + tanhf(c0 * (x + 0.044715f * x3)));
}
__device__ __forceinline__ float sigmoidf(float x) {
    return 1.0f / (1.0f + expf(-x));
}

// ---------------------------------------------------------------------------
// Generic fp32 SGEMM: C[M,N] = A[M,K] @ B[K,N]  (row-major, lda=K, ldb=N, ldc=N)
// BM=BN=128, BK=32, 256 threads, 8x8 microtiles.
// Requires: M % 128 == 0, K % 32 == 0, N % 4 == 0 (N guarded).
// Epilogues:
//   0: none
//   1: + bias[col]
//   2: gather-add + gelu:  v = gelu(acc + self[row/32][col] + nbr[nbIdx[row]][col])
// ---------------------------------------------------------------------------
#define EPI_NONE 0
#define EPI_BIAS 1
#define EPI_GATHER_GELU 2

template<int EPI>
__global__ __launch_bounds__(256)
void sgemm_kernel(const float* __restrict__ A, const float* __restrict__ B,
                  float* __restrict__ C, int M, int N, int K,
                  const float* __restrict__ bias,
                  const float* __restrict__ selfRows,   // ld = N
                  const float* __restrict__ nbRows,     // ld = N
                  const int*   __restrict__ nbIdx,
                  int nNodes)
{
    __shared__ float As[32][132];   // padded (+4) to kill store bank conflicts
    __shared__ float Bs[32][128];

    const int tid = threadIdx.x;
    const int tx = tid & 15;        // col dir
    const int ty = tid >> 4;        // row dir
    const int rowBase = blockIdx.y * 128;
    const int colBase = blockIdx.x * 128;

    float acc[8][8];
    #pragma unroll
    for (int i = 0; i < 8; i++)
        #pragma unroll
        for (int j = 0; j < 8; j++) acc[i][j] = 0.0f;

    for (int kt = 0; kt < K; kt += 32) {
        // A tile: 128 rows x 32 cols, transposed into As[k][m]
        #pragma unroll
        for (int i = 0; i < 4; i++) {
            int e  = tid + i * 256;       // float4 unit, 0..1023
            int r  = e >> 3;              // 8 float4 per row
            int c4 = (e & 7) * 4;
            float4 v = *reinterpret_cast<const float4*>(
                A + (size_t)(rowBase + r) * K + kt + c4);
            As[c4 + 0][r] = v.x; As[c4 + 1][r] = v.y;
            As[c4 + 2][r] = v.z; As[c4 + 3][r] = v.w;
        }
        // B tile: 32 rows x 128 cols
        #pragma unroll
        for (int i = 0; i < 4; i++) {
            int e  = tid + i * 256;
            int r  = e >> 5;              // 32 float4 per row
            int c4 = (e & 31) * 4;
            int gc = colBase + c4;
            float4 v = make_float4(0.f, 0.f, 0.f, 0.f);
            if (gc < N)
                v = *reinterpret_cast<const float4*>(B + (size_t)(kt + r) * N + gc);
            *reinterpret_cast<float4*>(&Bs[r][c4]) = v;
        }
        __syncthreads();

        #pragma unroll
        for (int k = 0; k < 32; k++) {
            float4 a0 = *reinterpret_cast<const float4*>(&As[k][ty * 8]);
            float4 a1 = *reinterpret_cast<const float4*>(&As[k][ty * 8 + 4]);
            float4 b0 = *reinterpret_cast<const float4*>(&Bs[k][tx * 8]);
            float4 b1 = *reinterpret_cast<const float4*>(&Bs[k][tx * 8 + 4]);
            float a[8] = {a0.x, a0.y, a0.z, a0.w, a1.x, a1.y, a1.z, a1.w};
            float b[8] = {b0.x, b0.y, b0.z, b0.w, b1.x, b1.y, b1.z, b1.w};
            #pragma unroll
            for (int i = 0; i < 8; i++)
                #pragma unroll
                for (int j = 0; j < 8; j++)
                    acc[i][j] += a[i] * b[j];
        }
        __syncthreads();
    }

    // epilogue + store (float4)
    #pragma unroll
    for (int i = 0; i < 8; i++) {
        int r = rowBase + ty * 8 + i;
        int n_node = 0, nb = 0;
        if (EPI == EPI_GATHER_GELU) {
            n_node = r >> 5;                       // K = 32 edges per node
            nb = nbIdx[r];
            if (nb < 0) nb += nNodes;              // python-style wrap for -1
        }
        #pragma unroll
        for (int j = 0; j < 8; j += 4) {
            int c = colBase + tx * 8 + j;
            if (c < N) {
                float v0 = acc[i][j + 0], v1 = acc[i][j + 1];
                float v2 = acc[i][j + 2], v3 = acc[i][j + 3];
                if (EPI == EPI_BIAS) {
                    float4 bb = *reinterpret_cast<const float4*>(bias + c);
                    v0 += bb.x; v1 += bb.y; v2 += bb.z; v3 += bb.w;
                }
                if (EPI == EPI_GATHER_GELU) {
                    float4 s4 = *reinterpret_cast<const float4*>(
                        selfRows + (size_t)n_node * N + c);
                    float4 n4 = *reinterpret_cast<const float4*>(
                        nbRows + (size_t)nb * N + c);
                    v0 = gelu_tanh(v0 + s4.x + n4.x);
                    v1 = gelu_tanh(v1 + s4.y + n4.y);
                    v2 = gelu_tanh(v2 + s4.z + n4.z);
                    v3 = gelu_tanh(v3 + s4.w + n4.w);
                }
                *reinterpret_cast<float4*>(C + (size_t)r * N + c) =
                    make_float4(v0, v1, v2, v3);
            }
        }
    }
}

// ---------------------------------------------------------------------------
// Block reduce over 128 threads
// ---------------------------------------------------------------------------
__device__ __forceinline__ float blockSum128(float v) {
    __shared__ float sred[4];
    v += __shfl_xor_sync(0xffffffffu, v, 16);
    v += __shfl_xor_sync(0xffffffffu, v, 8);
    v += __shfl_xor_sync(0xffffffffu, v, 4);
    v += __shfl_xor_sync(0xffffffffu, v, 2);
    v += __shfl_xor_sync(0xffffffffu, v, 1);
    if ((threadIdx.x & 31) == 0) sred[threadIdx.x >> 5] = v;
    __syncthreads();
    float t = sred[0] + sred[1] + sred[2] + sred[3];
    __syncthreads();
    return t;
}

// ---------------------------------------------------------------------------
// R1: masked mean over K, gate, residual, LN1 -> local1   (block = node, 128 thr)
// ---------------------------------------------------------------------------
__global__ __launch_bounds__(128)
void msg_reduce_ln1(const float* __restrict__ Msg, const float* __restrict__ local,
                    const float* __restrict__ gpre, const int* __restrict__ neigh,
                    const float* __restrict__ mask, const float* __restrict__ bg1,
                    const float* __restrict__ s, const float* __restrict__ b,
                    float* __restrict__ out)
{
    int n = blockIdx.x, c = threadIdx.x;
    float mk = mask[n];
    const float* mrow = Msg + ((size_t)n * KN) * LDIM + c;
    float sum = 0.f;
    #pragma unroll 4
    for (int k = 0; k < KN; k++) {
        int nb = neigh[n * KN + k];
        bool on = (mk != 0.f) && (nb != -1);
        float h = mrow[(size_t)k * LDIM];
        sum += on ? h : 0.f;
    }
    float upd = sum * (1.f / KN);
    float gate = sigmoidf(gpre[(size_t)n * LDIM + c] + bg1[c]);
    float x = local[(size_t)n * LDIM + c] + upd * gate;

    float mean = blockSum128(x) * (1.f / LDIM);
    float d = x - mean;
    float var = blockSum128(d * d) * (1.f / LDIM);
    out[(size_t)n * LDIM + c] = s[c] * d * rsqrtf(var + 1e-5f) + b[c];
}

// ---------------------------------------------------------------------------
// E1: G = silu(V) * U   (in-place into U)
// ---------------------------------------------------------------------------
__global__ __launch_bounds__(256)
void silu_mul_kernel(const float* __restrict__ V, float* __restrict__ U, size_t n)
{
    size_t i = (size_t)blockIdx.x * blockDim.x + threadIdx.x;
    size_t stride = (size_t)gridDim.x * blockDim.x;
    for (; i < n; i += stride) {
        float v = V[i];
        U[i] = U[i] * (v * sigmoidf(v));
    }
}

// ---------------------------------------------------------------------------
// R2: local2 = LN2(local1 + O + bo) -> d_out local half   (block = node)
// ---------------------------------------------------------------------------
__global__ __launch_bounds__(128)
void ln2_kernel(const float* __restrict__ L1, const float* __restrict__ O,
                const float* __restrict__ bo, const float* __restrict__ s,
                const float* __restrict__ b, float* __restrict__ out)
{
    int n = blockIdx.x, c = threadIdx.x;
    float x = L1[(size_t)n * LDIM + c] + O[(size_t)n * LDIM + c] + bo[c];
    float mean = blockSum128(x) * (1.f / LDIM);
    float d = x - mean;
    float var = blockSum128(d * d) * (1.f / LDIM);
    out[(size_t)n * LDIM + c] = s[c] * d * rsqrtf(var + 1e-5f) + b[c];
}

// ---------------------------------------------------------------------------
// R3: pair_out = LN3(pair + HP2 * sigmoid(Gp + bg2))   (warp per edge row)
// blockDim = (32, 8): 8 rows per block, 64 dims -> 2 per lane
// ---------------------------------------------------------------------------
__global__ __launch_bounds__(256)
void pair_ln3_kernel(const float* __restrict__ pairIn, const float* __restrict__ HP2,
                     const float* __restrict__ Gp, const float* __restrict__ bg2,
                     const float* __restrict__ s, const float* __restrict__ b,
                     float* __restrict__ out)
{
    int row = blockIdx.x * 8 + threadIdx.y;
    int c0 = threadIdx.x, c1 = threadIdx.x + 32;
    size_t base = (size_t)row * PDIM;

    float g0 = sigmoidf(Gp[base + c0] + bg2[c0]);
    float g1 = sigmoidf(Gp[base + c1] + bg2[c1]);
    float x0 = pairIn[base + c0] + HP2[base + c0] * g0;
    float x1 = pairIn[base + c1] + HP2[base + c1] * g1;

    float sum = x0 + x1;
    #pragma unroll
    for (int o = 16; o > 0; o >>= 1) sum += __shfl_xor_sync(0xffffffffu, sum, o);
    float mean = sum * (1.f / PDIM);
    float d0 = x0 - mean, d1 = x1 - mean;
    float v = d0 * d0 + d1 * d1;
    #pragma unroll
    for (int o = 16; o > 0; o >>= 1) v += __shfl_xor_sync(0xffffffffu, v, o);
    float inv = rsqrtf(v * (1.f / PDIM) + 1e-5f);
    out[base + c0] = s[c0] * d0 * inv + b[c0];
    out[base + c1] = s[c1] * d1 * inv + b[c1];
}

// ---------------------------------------------------------------------------
// Launch
// ---------------------------------------------------------------------------
extern "C" void kernel_launch(void* const* d_in, const int* in_sizes, int n_in,
                              void* d_out, int out_size)
{
    const float* local = (const float*)d_in[0];
    const float* pair  = (const float*)d_in[1];   // [N*K, 64] flat
    const int*   neigh = (const int*)  d_in[2];   // [N*K] flat
    const float* mask  = (const float*)d_in[3];
    const float* W1    = (const float*)d_in[4];   // [320,512]
    const float* W2    = (const float*)d_in[5];   // [512,128]
    const float* Wg1   = (const float*)d_in[6];
    const float* bg1   = (const float*)d_in[7];
    const float* ln1s  = (const float*)d_in[8];
    const float* ln1b  = (const float*)d_in[9];
    const float* Wu    = (const float*)d_in[10];
    const float* bu    = (const float*)d_in[11];
    const float* Wv    = (const float*)d_in[12];
    const float* bv    = (const float*)d_in[13];
    const float* Wo    = (const float*)d_in[14];
    const float* bo    = (const float*)d_in[15];
    const float* ln2s  = (const float*)d_in[16];
    const float* ln2b  = (const float*)d_in[17];
    const float* W1p   = (const float*)d_in[18];  // [320,128]
    const float* W2p   = (const float*)d_in[19];  // [128,64]
    const float* Wg2   = (const float*)d_in[20];  // [64,64]
    const float* bg2   = (const float*)d_in[21];
    const float* ln3s  = (const float*)d_in[22];
    const float* ln3b  = (const float*)d_in[23];

    float* outLocal = (float*)d_out;
    float* outPair  = outLocal + (size_t)NNODES * LDIM;

    float* pool = nullptr;
    cudaGetSymbolAddress((void**)&pool, g_pool);
    float* aself = pool + F_ASELF;
    float* anb   = pool + F_ANB;
    float* gpre  = pool + F_GPRE;
    float* hg    = pool + F_HG;
    float* msg   = pool + F_MSG;
    float* l1    = pool + F_L1;
    float* u     = pool + F_U;
    float* v     = pool + F_V;
    float* o     = pool + F_O;
    float* bself = pool + F_BSELF;
    float* bnb   = pool + F_BNB;
    float* hpg   = pool + F_HPG;
    float* hp2   = pool + F_HP2;
    float* gp    = pool + F_GP;

    dim3 blk(256);
    auto grid = [](int M, int N) { return dim3((N + 127) / 128, M / 128); };

    // --- Phase 1: message passing + local updates ---
    // Aself = local @ W1[0:128,:], Anb = local @ W1[128:256,:], gate_pre = local @ Wg1
    sgemm_kernel<EPI_NONE><<<grid(NNODES, 512), blk>>>(local, W1,            aself, NNODES, 512, 128, nullptr, nullptr, nullptr, nullptr, 0);
    sgemm_kernel<EPI_NONE><<<grid(NNODES, 512), blk>>>(local, W1 + 128*512,  anb,   NNODES, 512, 128, nullptr, nullptr, nullptr, nullptr, 0);
    sgemm_kernel<EPI_NONE><<<grid(NNODES, 128), blk>>>(local, Wg1,           gpre,  NNODES, 128, 128, nullptr, nullptr, nullptr, nullptr, 0);
    // Hg = gelu(pair @ W1[256:320,:] + Aself[n] + Anb[nb])
    sgemm_kernel<EPI_GATHER_GELU><<<grid(NKROWS, 512), blk>>>(pair, W1 + 256*512, hg, NKROWS, 512, 64, nullptr, aself, anb, neigh, NNODES);
    // Msg = Hg @ W2
    sgemm_kernel<EPI_NONE><<<grid(NKROWS, 128), blk>>>(hg, W2, msg, NKROWS, 128, 512, nullptr, nullptr, nullptr, nullptr, 0);
    // masked mean + gate + residual + LN1 -> local1
    msg_reduce_ln1<<<NNODES, 128>>>(msg, local, gpre, neigh, mask, bg1, ln1s, ln1b, l1);
    // Gated MLP
    sgemm_kernel<EPI_BIAS><<<grid(NNODES, 512), blk>>>(l1, Wu, u, NNODES, 512, 128, bu, nullptr, nullptr, nullptr, 0);
    sgemm_kernel<EPI_BIAS><<<grid(NNODES, 512), blk>>>(l1, Wv, v, NNODES, 512, 128, bv, nullptr, nullptr, nullptr, 0);
    silu_mul_kernel<<<8192, 256>>>(v, u, (size_t)NNODES * 512);
    sgemm_kernel<EPI_NONE><<<grid(NNODES, 128), blk>>>(u, Wo, o, NNODES, 128, 512, nullptr, nullptr, nullptr, nullptr, 0);
    ln2_kernel<<<NNODES, 128>>>(l1, o, bo, ln2s, ln2b, outLocal);   // local2 -> output

    // --- Phase 2: pair update (uses post-LN2 local from d_out) ---
    sgemm_kernel<EPI_NONE><<<grid(NNODES, 128), blk>>>(outLocal, W1p,           bself, NNODES, 128, 128, nullptr, nullptr, nullptr, nullptr, 0);
    sgemm_kernel<EPI_NONE><<<grid(NNODES, 128), blk>>>(outLocal, W1p + 128*128, bnb,   NNODES, 128, 128, nullptr, nullptr, nullptr, nullptr, 0);
    sgemm_kernel<EPI_GATHER_GELU><<<grid(NKROWS, 128), blk>>>(pair, W1p + 256*128, hpg, NKROWS, 128, 64, nullptr, bself, bnb, neigh, NNODES);
    sgemm_kernel<EPI_NONE><<<grid(NKROWS, 64), blk>>>(hpg, W2p, hp2, NKROWS, 64, 128, nullptr, nullptr, nullptr, nullptr, 0);
    sgemm_kernel<EPI_NONE><<<grid(NKROWS, 64), blk>>>(pair, Wg2, gp,  NKROWS, 64, 64,  nullptr, nullptr, nullptr, nullptr, 0);
    pair_ln3_kernel<<<NKROWS / 8, dim3(32, 8)>>>(pair, hp2, gp, bg2, ln3s, ln3b, outPair);
}

// round 5
// speedup vs baseline: 1.9714x; 1.9714x over previous
#include <cuda_runtime.h>
#include <math.h>
#include <stdint.h>

// ---------------------------------------------------------------------------
// Problem constants
// ---------------------------------------------------------------------------
#define NNODES 16384
#define KN     32
#define LDIM   128
#define PDIM   64
#define NKROWS (NNODES * KN)          // 524288 edge rows

// ---------------------------------------------------------------------------
// Scratch pool (static device memory; ~1.50 GB, aliased by liveness)
// ---------------------------------------------------------------------------
constexpr size_t F_ASELF = 0;                                   // [16384,512]
constexpr size_t F_ANB   = F_ASELF + 16384UL * 512;             // [16384,512]
constexpr size_t F_GPRE  = F_ANB   + 16384UL * 512;             // [16384,128]
constexpr size_t F_L1    = F_GPRE  + 16384UL * 128;             // [16384,128]
constexpr size_t F_U     = F_L1    + 16384UL * 128;             // [16384,512]
constexpr size_t F_V     = F_U     + 16384UL * 512;             // [16384,512]
constexpr size_t F_O     = F_V     + 16384UL * 512;             // [16384,128]
constexpr size_t F_MSG   = F_O     + 16384UL * 128;             // [524288,128]
constexpr size_t F_HG    = F_MSG   + 524288UL * 128;            // [524288,512]
constexpr size_t POOL_FLOATS = F_HG + 524288UL * 512;           // 375,390,208

// Phase-2 aliases (phase-1 buffers dead by then)
constexpr size_t F_BSELF = F_ASELF;
constexpr size_t F_BNB   = F_ANB;
constexpr size_t F_HPG   = F_HG;
constexpr size_t F_HP2   = F_HG + 524288UL * 128;
constexpr size_t F_GP    = F_HP2 + 524288UL * 64;

__device__ float g_pool[POOL_FLOATS];

// ---------------------------------------------------------------------------
// Math helpers (match JAX: gelu approximate=True(tanh), silu, sigmoid)
// ---------------------------------------------------------------------------
__device__ __forceinline__ float gelu_tanh(float x) {
    const float c0 = 0.7978845608028654f;   // sqrt(2/pi)
    float x3 = x * x * x;
    return 0.5f * x * (1.0f + tanhf(c0 * (x + 0.044715f * x3)));
}
__device__ __forceinline__ float sigmoidf(float x) {
    return 1.0f / (1.0f + expf(-x));
}
__device__ __forceinline__ uint32_t f2tf(float f) {
    uint32_t r;
    asm("cvt.rna.tf32.f32 %0, %1;" : "=r"(r) : "f"(f));
    return r;
}
__device__ __forceinline__ void mma_tf32(float* c, const uint32_t* a, const uint32_t* b) {
    asm volatile(
        "mma.sync.aligned.m16n8k8.row.col.f32.tf32.tf32.f32 "
        "{%0,%1,%2,%3}, {%4,%5,%6,%7}, {%8,%9}, {%0,%1,%2,%3};"
        : "+f"(c[0]), "+f"(c[1]), "+f"(c[2]), "+f"(c[3])
        : "r"(a[0]), "r"(a[1]), "r"(a[2]), "r"(a[3]), "r"(b[0]), "r"(b[1]));
}

// ---------------------------------------------------------------------------
// TF32 tensor-core GEMM: C[M,N] = A[M,K] @ B[K,N]  (row-major)
// BM=BN=128, BK=32, 256 threads (8 warps, 2x4), warp tile 64x32.
// Requires: M % 128 == 0, K % 32 == 0, N % 8 == 0 (N guarded vs 128).
// Epilogues: 0 none, 1 +bias[col], 2 gelu(acc + self[row/32] + nbr[nbIdx[row]])
// ---------------------------------------------------------------------------
#define EPI_NONE 0
#define EPI_BIAS 1
#define EPI_GATHER_GELU 2

#define APAD 36    // A smem row stride (m-major [128][36]) -> conflict-free frag loads
#define BPAD 136   // B smem row stride (k-major [32][136]) -> conflict-free frag loads

template<int EPI>
__global__ __launch_bounds__(256)
void tgemm_kernel(const float* __restrict__ A, const float* __restrict__ B,
                  float* __restrict__ C, int M, int N, int K,
                  const float* __restrict__ bias,
                  const float* __restrict__ selfRows,   // ld = N
                  const float* __restrict__ nbRows,     // ld = N
                  const int*   __restrict__ nbIdx,
                  int nNodes)
{
    __shared__ __align__(16) uint32_t As[128][APAD];   // [m][k]
    __shared__ __align__(16) uint32_t Bs[32][BPAD];    // [k][n]

    const int tid  = threadIdx.x;
    const int lane = tid & 31;
    const int wid  = tid >> 5;
    const int gid  = lane >> 2;    // 0..7
    const int tig  = lane & 3;     // 0..3
    const int wm   = wid >> 2;     // 0..1  (64 rows each)
    const int wn   = wid & 3;      // 0..3  (32 cols each)
    const int rowBase = blockIdx.y * 128;
    const int colBase = blockIdx.x * 128;

    float acc[4][4][4];            // [mf][nf][creg]
    #pragma unroll
    for (int i = 0; i < 4; i++)
        #pragma unroll
        for (int j = 0; j < 4; j++)
            #pragma unroll
            for (int q = 0; q < 4; q++) acc[i][j][q] = 0.0f;

    for (int kt = 0; kt < K; kt += 32) {
        // Stage A tile: 128 rows x 32 k. Coalesced 128B/8-thread row chunks;
        // convert to tf32, store uint4 (conflict-free per phase).
        #pragma unroll
        for (int i = 0; i < 4; i++) {
            int r  = (tid >> 3) + i * 32;
            int c4 = (tid & 7) * 4;
            float4 v = *reinterpret_cast<const float4*>(
                A + (size_t)(rowBase + r) * K + kt + c4);
            uint4 u = make_uint4(f2tf(v.x), f2tf(v.y), f2tf(v.z), f2tf(v.w));
            *reinterpret_cast<uint4*>(&As[r][c4]) = u;
        }
        // Stage B tile: 32 k x 128 n (guarded vs N)
        #pragma unroll
        for (int i = 0; i < 4; i++) {
            int r  = (tid >> 5) + i * 8;
            int c4 = (tid & 31) * 4;
            int gc = colBase + c4;
            float4 v = make_float4(0.f, 0.f, 0.f, 0.f);
            if (gc < N)
                v = *reinterpret_cast<const float4*>(B + (size_t)(kt + r) * N + gc);
            uint4 u = make_uint4(f2tf(v.x), f2tf(v.y), f2tf(v.z), f2tf(v.w));
            *reinterpret_cast<uint4*>(&Bs[r][c4]) = u;
        }
        __syncthreads();

        #pragma unroll
        for (int ks = 0; ks < 4; ks++) {
            const int k0 = ks * 8;
            uint32_t af[4][4], bf[4][2];
            #pragma unroll
            for (int mf = 0; mf < 4; mf++) {
                int m0 = wm * 64 + mf * 16 + gid;
                af[mf][0] = As[m0    ][k0 + tig];
                af[mf][1] = As[m0 + 8][k0 + tig];
                af[mf][2] = As[m0    ][k0 + tig + 4];
                af[mf][3] = As[m0 + 8][k0 + tig + 4];
            }
            #pragma unroll
            for (int nf = 0; nf < 4; nf++) {
                int n0 = wn * 32 + nf * 8 + gid;
                bf[nf][0] = Bs[k0 + tig    ][n0];
                bf[nf][1] = Bs[k0 + tig + 4][n0];
            }
            #pragma unroll
            for (int mf = 0; mf < 4; mf++)
                #pragma unroll
                for (int nf = 0; nf < 4; nf++)
                    mma_tf32(acc[mf][nf], af[mf], bf[nf]);
        }
        __syncthreads();
    }

    // Epilogue + store. C frag: c0,c1 = row g cols 2t,2t+1; c2,c3 = row g+8.
    #pragma unroll
    for (int mf = 0; mf < 4; mf++) {
        int r0 = rowBase + wm * 64 + mf * 16 + gid;
        int r1 = r0 + 8;
        int nb0 = 0, nb1 = 0, node0 = 0, node1 = 0;
        if (EPI == EPI_GATHER_GELU) {
            node0 = r0 >> 5; node1 = r1 >> 5;   // K=32 edges per node
            nb0 = nbIdx[r0]; if (nb0 < 0) nb0 += nNodes;
            nb1 = nbIdx[r1]; if (nb1 < 0) nb1 += nNodes;
        }
        #pragma unroll
        for (int nf = 0; nf < 4; nf++) {
            int c = colBase + wn * 32 + nf * 8 + 2 * tig;
            if (c < N) {
                float v00 = acc[mf][nf][0], v01 = acc[mf][nf][1];   // row r0
                float v10 = acc[mf][nf][2], v11 = acc[mf][nf][3];   // row r1
                if (EPI == EPI_BIAS) {
                    float2 bb = *reinterpret_cast<const float2*>(bias + c);
                    v00 += bb.x; v01 += bb.y; v10 += bb.x; v11 += bb.y;
                }
                if (EPI == EPI_GATHER_GELU) {
                    float2 s0 = *reinterpret_cast<const float2*>(selfRows + (size_t)node0 * N + c);
                    float2 n0v = *reinterpret_cast<const float2*>(nbRows + (size_t)nb0 * N + c);
                    float2 s1 = *reinterpret_cast<const float2*>(selfRows + (size_t)node1 * N + c);
                    float2 n1v = *reinterpret_cast<const float2*>(nbRows + (size_t)nb1 * N + c);
                    v00 = gelu_tanh(v00 + s0.x + n0v.x);
                    v01 = gelu_tanh(v01 + s0.y + n0v.y);
                    v10 = gelu_tanh(v10 + s1.x + n1v.x);
                    v11 = gelu_tanh(v11 + s1.y + n1v.y);
                }
                *reinterpret_cast<float2*>(C + (size_t)r0 * N + c) = make_float2(v00, v01);
                *reinterpret_cast<float2*>(C + (size_t)r1 * N + c) = make_float2(v10, v11);
            }
        }
    }
}

// ---------------------------------------------------------------------------
// Block reduce over 128 threads
// ---------------------------------------------------------------------------
__device__ __forceinline__ float blockSum128(float v) {
    __shared__ float sred[4];
    v += __shfl_xor_sync(0xffffffffu, v, 16);
    v += __shfl_xor_sync(0xffffffffu, v, 8);
    v += __shfl_xor_sync(0xffffffffu, v, 4);
    v += __shfl_xor_sync(0xffffffffu, v, 2);
    v += __shfl_xor_sync(0xffffffffu, v, 1);
    if ((threadIdx.x & 31) == 0) sred[threadIdx.x >> 5] = v;
    __syncthreads();
    float t = sred[0] + sred[1] + sred[2] + sred[3];
    __syncthreads();
    return t;
}

// ---------------------------------------------------------------------------
// R1: masked mean over K, gate, residual, LN1 -> local1   (block = node)
// ---------------------------------------------------------------------------
__global__ __launch_bounds__(128)
void msg_reduce_ln1(const float* __restrict__ Msg, const float* __restrict__ local,
                    const float* __restrict__ gpre, const int* __restrict__ neigh,
                    const float* __restrict__ mask, const float* __restrict__ bg1,
                    const float* __restrict__ s, const float* __restrict__ b,
                    float* __restrict__ out)
{
    int n = blockIdx.x, c = threadIdx.x;
    float mk = mask[n];
    const float* mrow = Msg + ((size_t)n * KN) * LDIM + c;
    float sum = 0.f;
    #pragma unroll 4
    for (int k = 0; k < KN; k++) {
        int nb = neigh[n * KN + k];
        bool on = (mk != 0.f) && (nb != -1);
        float h = mrow[(size_t)k * LDIM];
        sum += on ? h : 0.f;
    }
    float upd = sum * (1.f / KN);
    float gate = sigmoidf(gpre[(size_t)n * LDIM + c] + bg1[c]);
    float x = local[(size_t)n * LDIM + c] + upd * gate;

    float mean = blockSum128(x) * (1.f / LDIM);
    float d = x - mean;
    float var = blockSum128(d * d) * (1.f / LDIM);
    out[(size_t)n * LDIM + c] = s[c] * d * rsqrtf(var + 1e-5f) + b[c];
}

// ---------------------------------------------------------------------------
// E1: G = silu(V) * U   (in-place into U)
// ---------------------------------------------------------------------------
__global__ __launch_bounds__(256)
void silu_mul_kernel(const float* __restrict__ V, float* __restrict__ U, size_t n)
{
    size_t i = (size_t)blockIdx.x * blockDim.x + threadIdx.x;
    size_t stride = (size_t)gridDim.x * blockDim.x;
    for (; i < n; i += stride) {
        float v = V[i];
        U[i] = U[i] * (v * sigmoidf(v));
    }
}

// ---------------------------------------------------------------------------
// R2: local2 = LN2(local1 + O + bo) -> d_out local half
// ---------------------------------------------------------------------------
__global__ __launch_bounds__(128)
void ln2_kernel(const float* __restrict__ L1, const float* __restrict__ O,
                const float* __restrict__ bo, const float* __restrict__ s,
                const float* __restrict__ b, float* __restrict__ out)
{
    int n = blockIdx.x, c = threadIdx.x;
    float x = L1[(size_t)n * LDIM + c] + O[(size_t)n * LDIM + c] + bo[c];
    float mean = blockSum128(x) * (1.f / LDIM);
    float d = x - mean;
    float var = blockSum128(d * d) * (1.f / LDIM);
    out[(size_t)n * LDIM + c] = s[c] * d * rsqrtf(var + 1e-5f) + b[c];
}

// ---------------------------------------------------------------------------
// R3: pair_out = LN3(pair + HP2 * sigmoid(Gp + bg2))   (warp per edge row)
// ---------------------------------------------------------------------------
__global__ __launch_bounds__(256)
void pair_ln3_kernel(const float* __restrict__ pairIn, const float* __restrict__ HP2,
                     const float* __restrict__ Gp, const float* __restrict__ bg2,
                     const float* __restrict__ s, const float* __restrict__ b,
                     float* __restrict__ out)
{
    int row = blockIdx.x * 8 + threadIdx.y;
    int c0 = threadIdx.x, c1 = threadIdx.x + 32;
    size_t base = (size_t)row * PDIM;

    float g0 = sigmoidf(Gp[base + c0] + bg2[c0]);
    float g1 = sigmoidf(Gp[base + c1] + bg2[c1]);
    float x0 = pairIn[base + c0] + HP2[base + c0] * g0;
    float x1 = pairIn[base + c1] + HP2[base + c1] * g1;

    float sum = x0 + x1;
    #pragma unroll
    for (int o = 16; o > 0; o >>= 1) sum += __shfl_xor_sync(0xffffffffu, sum, o);
    float mean = sum * (1.f / PDIM);
    float d0 = x0 - mean, d1 = x1 - mean;
    float v = d0 * d0 + d1 * d1;
    #pragma unroll
    for (int o = 16; o > 0; o >>= 1) v += __shfl_xor_sync(0xffffffffu, v, o);
    float inv = rsqrtf(v * (1.f / PDIM) + 1e-5f);
    out[base + c0] = s[c0] * d0 * inv + b[c0];
    out[base + c1] = s[c1] * d1 * inv + b[c1];
}

// ---------------------------------------------------------------------------
// Launch
// ---------------------------------------------------------------------------
extern "C" void kernel_launch(void* const* d_in, const int* in_sizes, int n_in,
                              void* d_out, int out_size)
{
    const float* local = (const float*)d_in[0];
    const float* pair  = (const float*)d_in[1];   // [N*K, 64] flat
    const int*   neigh = (const int*)  d_in[2];   // [N*K] flat
    const float* mask  = (const float*)d_in[3];
    const float* W1    = (const float*)d_in[4];   // [320,512]
    const float* W2    = (const float*)d_in[5];   // [512,128]
    const float* Wg1   = (const float*)d_in[6];
    const float* bg1   = (const float*)d_in[7];
    const float* ln1s  = (const float*)d_in[8];
    const float* ln1b  = (const float*)d_in[9];
    const float* Wu    = (const float*)d_in[10];
    const float* bu    = (const float*)d_in[11];
    const float* Wv    = (const float*)d_in[12];
    const float* bv    = (const float*)d_in[13];
    const float* Wo    = (const float*)d_in[14];
    const float* bo    = (const float*)d_in[15];
    const float* ln2s  = (const float*)d_in[16];
    const float* ln2b  = (const float*)d_in[17];
    const float* W1p   = (const float*)d_in[18];  // [320,128]
    const float* W2p   = (const float*)d_in[19];  // [128,64]
    const float* Wg2   = (const float*)d_in[20];  // [64,64]
    const float* bg2   = (const float*)d_in[21];
    const float* ln3s  = (const float*)d_in[22];
    const float* ln3b  = (const float*)d_in[23];

    float* outLocal = (float*)d_out;
    float* outPair  = outLocal + (size_t)NNODES * LDIM;

    float* pool = nullptr;
    cudaGetSymbolAddress((void**)&pool, g_pool);
    float* aself = pool + F_ASELF;
    float* anb   = pool + F_ANB;
    float* gpre  = pool + F_GPRE;
    float* hg    = pool + F_HG;
    float* msg   = pool + F_MSG;
    float* l1    = pool + F_L1;
    float* u     = pool + F_U;
    float* v     = pool + F_V;
    float* o     = pool + F_O;
    float* bself = pool + F_BSELF;
    float* bnb   = pool + F_BNB;
    float* hpg   = pool + F_HPG;
    float* hp2   = pool + F_HP2;
    float* gp    = pool + F_GP;

    dim3 blk(256);
    auto grid = [](int M, int N) { return dim3((N + 127) / 128, M / 128); };

    // --- Phase 1: message passing + local updates ---
    tgemm_kernel<EPI_NONE><<<grid(NNODES, 512), blk>>>(local, W1,            aself, NNODES, 512, 128, nullptr, nullptr, nullptr, nullptr, 0);
    tgemm_kernel<EPI_NONE><<<grid(NNODES, 512), blk>>>(local, W1 + 128*512,  anb,   NNODES, 512, 128, nullptr, nullptr, nullptr, nullptr, 0);
    tgemm_kernel<EPI_NONE><<<grid(NNODES, 128), blk>>>(local, Wg1,           gpre,  NNODES, 128, 128, nullptr, nullptr, nullptr, nullptr, 0);
    // Hg = gelu(pair @ W1[256:320,:] + Aself[n] + Anb[nb])
    tgemm_kernel<EPI_GATHER_GELU><<<grid(NKROWS, 512), blk>>>(pair, W1 + 256*512, hg, NKROWS, 512, 64, nullptr, aself, anb, neigh, NNODES);
    // Msg = Hg @ W2
    tgemm_kernel<EPI_NONE><<<grid(NKROWS, 128), blk>>>(hg, W2, msg, NKROWS, 128, 512, nullptr, nullptr, nullptr, nullptr, 0);
    // masked mean + gate + residual + LN1 -> local1
    msg_reduce_ln1<<<NNODES, 128>>>(msg, local, gpre, neigh, mask, bg1, ln1s, ln1b, l1);
    // Gated MLP
    tgemm_kernel<EPI_BIAS><<<grid(NNODES, 512), blk>>>(l1, Wu, u, NNODES, 512, 128, bu, nullptr, nullptr, nullptr, 0);
    tgemm_kernel<EPI_BIAS><<<grid(NNODES, 512), blk>>>(l1, Wv, v, NNODES, 512, 128, bv, nullptr, nullptr, nullptr, 0);
    silu_mul_kernel<<<8192, 256>>>(v, u, (size_t)NNODES * 512);
    tgemm_kernel<EPI_NONE><<<grid(NNODES, 128), blk>>>(u, Wo, o, NNODES, 128, 512, nullptr, nullptr, nullptr, nullptr, 0);
    ln2_kernel<<<NNODES, 128>>>(l1, o, bo, ln2s, ln2b, outLocal);   // local2 -> output

    // --- Phase 2: pair update (uses post-LN2 local from d_out) ---
    tgemm_kernel<EPI_NONE><<<grid(NNODES, 128), blk>>>(outLocal, W1p,           bself, NNODES, 128, 128, nullptr, nullptr, nullptr, nullptr, 0);
    tgemm_kernel<EPI_NONE><<<grid(NNODES, 128), blk>>>(outLocal, W1p + 128*128, bnb,   NNODES, 128, 128, nullptr, nullptr, nullptr, nullptr, 0);
    tgemm_kernel<EPI_GATHER_GELU><<<grid(NKROWS, 128), blk>>>(pair, W1p + 256*128, hpg, NKROWS, 128, 64, nullptr, bself, bnb, neigh, NNODES);
    tgemm_kernel<EPI_NONE><<<grid(NKROWS, 64), blk>>>(hpg, W2p, hp2, NKROWS, 64, 128, nullptr, nullptr, nullptr, nullptr, 0);
    tgemm_kernel<EPI_NONE><<<grid(NKROWS, 64), blk>>>(pair, Wg2, gp,  NKROWS, 64, 64,  nullptr, nullptr, nullptr, nullptr, 0);
    pair_ln3_kernel<<<NKROWS / 8, dim3(32, 8)>>>(pair, hp2, gp, bg2, ln3s, ln3b, outPair);
}